// round 16
// baseline (speedup 1.0000x reference)
#include <cuda_runtime.h>
#include <math.h>

#define Tn   64
#define Bn   16
#define Nn   256
#define Wn   64
#define Rn   4
#define INn  64
#define IFS  471
#define IFP  472
#define EPSf 1e-6f
#define NT   512

// global scratch (allocation-free)
__device__ float g_link[Bn * Nn * Nn];   // 4 MB, L2-resident; lk[row*256+col]
__device__ float g_Wifp[256 * IFP];      // W_if repacked pitch 471 -> 472
// exchange mailbox: [batch][buf][cta]: [0..255]=bwd partial, [256..383]=fwd half
__device__ float4 g_xch[Bn][2][2][384];

struct SMem {
    float  mem[Nn][Wn + 1];          // pitch 65, conflict-free
    float4 Lst[2][32 * 65];          // staging tiles (two 32-row groups)
    float4 scratch4[512];
    float4 fwdv[Nn];
    float4 bwdv[Nn];
    float4 rcv[Nn];
    float4 rwv[Nn];
    float4 keyn4[Wn];
    float  rvec[256];
    float  ctrl[INn + 256];
    float  h[256];
    float  nn[256];
    float  z[IFP];
    float  ww[Nn];
    float  prec[Nn];
    float  usage[Nn];
    float  alloc_[Nn];
    unsigned long long skey[Nn];
    float  wkeyn[Wn];
    float  er[Wn];
    float  wv[Wn];
    float  wc[Nn];
    float  red[80];
    float  rstr[Rn];
    float  freeg[Rn];
    float  modes[3][Rn];
    float  wstr, allocg, writeg;
};

__device__ __forceinline__ float sigm_(float x) { return 1.0f / (1.0f + expf(-x)); }
__device__ __forceinline__ float softp_(float x) { return fmaxf(x, 0.0f) + log1pf(expf(-fabsf(x))); }

// ---- packed f32x2 helpers (FFMA2 is PTX-only; ptxas never auto-fuses) ----
__device__ __forceinline__ unsigned long long pk2(float a, float b) {
    unsigned long long r;
    asm("mov.b64 %0, {%1, %2};" : "=l"(r) : "f"(a), "f"(b));
    return r;
}
__device__ __forceinline__ void up2(unsigned long long v, float& a, float& b) {
    asm("mov.b64 {%0, %1}, %2;" : "=f"(a), "=f"(b) : "l"(v));
}
__device__ __forceinline__ unsigned long long ffma2_(unsigned long long a,
                                                     unsigned long long b,
                                                     unsigned long long c) {
    unsigned long long d;
    asm("fma.rn.f32x2 %0, %1, %2, %3;" : "=l"(d) : "l"(a), "l"(b), "l"(c));
    return d;
}

// block reductions for 16 warps
__device__ __forceinline__ float bsum(float* red, float v, int tid) {
#pragma unroll
    for (int o = 16; o; o >>= 1) v += __shfl_xor_sync(0xffffffffu, v, o);
    if ((tid & 31) == 0) red[tid >> 5] = v;
    __syncthreads();
    if (tid == 0) {
        float a = red[0];
#pragma unroll
        for (int i = 1; i < 16; ++i) a += red[i];
        red[72] = a;
    }
    __syncthreads();
    return red[72];
}
__device__ __forceinline__ float bmax(float* red, float v, int tid) {
#pragma unroll
    for (int o = 16; o; o >>= 1) v = fmaxf(v, __shfl_xor_sync(0xffffffffu, v, o));
    if ((tid & 31) == 0) red[tid >> 5] = v;
    __syncthreads();
    if (tid == 0) {
        float a = red[0];
#pragma unroll
        for (int i = 1; i < 16; ++i) a = fmaxf(a, red[i]);
        red[72] = a;
    }
    __syncthreads();
    return red[72];
}
__device__ __forceinline__ void bred4(float* red, float* v, int tid, int domax) {
#pragma unroll
    for (int o = 16; o; o >>= 1) {
#pragma unroll
        for (int r = 0; r < 4; ++r) {
            float w = __shfl_xor_sync(0xffffffffu, v[r], o);
            v[r] = domax ? fmaxf(v[r], w) : (v[r] + w);
        }
    }
    if ((tid & 31) == 0) {
#pragma unroll
        for (int r = 0; r < 4; ++r) red[(tid >> 5) * 4 + r] = v[r];
    }
    __syncthreads();
    if (tid < 4) {
        float a = red[tid];
#pragma unroll
        for (int w = 1; w < 16; ++w) {
            float b = red[w * 4 + tid];
            a = domax ? fmaxf(a, b) : (a + b);
        }
        red[64 + tid] = a;
    }
    __syncthreads();
#pragma unroll
    for (int r = 0; r < 4; ++r) v[r] = red[64 + r];
}

__global__ void repack_kernel(const float* __restrict__ Wif) {
    int i = blockIdx.x;
    int j = threadIdx.x;
    if (j < IFP) g_Wifp[i * IFP + j] = (j < IFS) ? Wif[i * IFS + j] : 0.0f;
}

__global__ void __launch_bounds__(NT, 1) __cluster_dims__(2, 1, 1)
dnc_kernel(const float* __restrict__ x, const float* __restrict__ W1,
           const float* __restrict__ b1, const float* __restrict__ W2,
           const float* __restrict__ b2, const float* __restrict__ bif,
           const float* __restrict__ Wout, const float* __restrict__ Wmem,
           float* __restrict__ out) {
    extern __shared__ char smraw[];
    SMem* s = (SMem*)smraw;
    const int tid = threadIdx.x;
    const int lane = tid & 31, warp = tid >> 5;
    const int b = blockIdx.x >> 1;     // batch
    const int hf = blockIdx.x & 1;     // link row half owned by this CTA
    const int hfbase = hf * 128;
    float* lk = g_link + b * (Nn * Nn);

    // init carries
    {
        float4 z4 = make_float4(0.f, 0.f, 0.f, 0.f);
        float4* lk4 = (float4*)(lk + hfbase * Nn);
        for (int i = tid; i < 128 * Nn / 4; i += NT) lk4[i] = z4;
        if (tid < 256) {
#pragma unroll 8
            for (int w = 0; w < Wn; ++w) s->mem[tid][w] = EPSf;
            s->usage[tid] = 0.0f;
            s->ww[tid] = 0.0f;
            s->prec[tid] = 0.0f;
            s->rwv[tid] = z4;
            s->rvec[tid] = 0.0f;
        }
    }
    __syncthreads();

    float* sc = (float*)s->scratch4;
    const ulonglong2* rw2 = (const ulonglong2*)s->rwv;

    for (int t = 0; t < Tn; ++t) {
        // P1: controller input
        if (tid < INn) s->ctrl[tid] = x[(t * Bn + b) * INn + tid];
        if (tid < 256) s->ctrl[INn + tid] = s->rvec[tid];
        __syncthreads();

        // P2: h = tanh(ctrl @ W1 + b1), 320x256 (8 segments of 40), FFMA2
        {
            int sg = tid >> 6, q = tid & 63;
            const ulonglong2* Wp = (const ulonglong2*)W1;
            unsigned long long a01 = 0ull, a23 = 0ull;
            int i0 = sg * 40;
#pragma unroll 8
            for (int i = i0; i < i0 + 40; ++i) {
                unsigned long long cc = pk2(s->ctrl[i], s->ctrl[i]);
                ulonglong2 w2 = Wp[i * 64 + q];
                a01 = ffma2_(cc, w2.x, a01);
                a23 = ffma2_(cc, w2.y, a23);
            }
            ((ulonglong2*)s->scratch4)[sg * 64 + q] = make_ulonglong2(a01, a23);
        }
        __syncthreads();
        if (tid < 256) {
            int q = tid >> 2, c = tid & 3;
            float v = b1[tid];
#pragma unroll
            for (int sg = 0; sg < 8; ++sg) v += sc[(sg * 64 + q) * 4 + c];
            s->h[tid] = tanhf(v);
        }
        __syncthreads();

        // P3: nn = tanh(h @ W2 + b2), 256x256 (8 segments of 32), FFMA2
        {
            int sg = tid >> 6, q = tid & 63;
            const ulonglong2* Wp = (const ulonglong2*)W2;
            unsigned long long a01 = 0ull, a23 = 0ull;
            int i0 = sg * 32;
#pragma unroll 8
            for (int i = i0; i < i0 + 32; ++i) {
                unsigned long long cc = pk2(s->h[i], s->h[i]);
                ulonglong2 w2 = Wp[i * 64 + q];
                a01 = ffma2_(cc, w2.x, a01);
                a23 = ffma2_(cc, w2.y, a23);
            }
            ((ulonglong2*)s->scratch4)[sg * 64 + q] = make_ulonglong2(a01, a23);
        }
        __syncthreads();
        if (tid < 256) {
            int q = tid >> 2, c = tid & 3;
            float v = b2[tid];
#pragma unroll
            for (int sg = 0; sg < 8; ++sg) v += sc[(sg * 64 + q) * 4 + c];
            s->nn[tid] = tanhf(v);
        }
        __syncthreads();

        // P4 FUSED: z = nn @ W_if + b_if, rounds A and B concurrent, FFMA2
        if (tid < 256) {
            int sg = tid >> 6, q = tid & 63;
            const ulonglong2* Wp = (const ulonglong2*)g_Wifp;
            unsigned long long a01 = 0ull, a23 = 0ull;
            int i0 = sg * 64;
#pragma unroll 8
            for (int i = i0; i < i0 + 64; ++i) {
                unsigned long long cc = pk2(s->nn[i], s->nn[i]);
                ulonglong2 w2 = Wp[i * 118 + q];
                a01 = ffma2_(cc, w2.x, a01);
                a23 = ffma2_(cc, w2.y, a23);
            }
            ((ulonglong2*)s->scratch4)[sg * 64 + q] = make_ulonglong2(a01, a23);
        } else {
            int tid2 = tid - 256;
            int sg = tid2 >> 6, q0 = tid2 & 63;
            if (q0 < 54) {
                const ulonglong2* Wp = (const ulonglong2*)g_Wifp;
                unsigned long long a01 = 0ull, a23 = 0ull;
                int i0 = sg * 64, q = 64 + q0;
#pragma unroll 8
                for (int i = i0; i < i0 + 64; ++i) {
                    unsigned long long cc = pk2(s->nn[i], s->nn[i]);
                    ulonglong2 w2 = Wp[i * 118 + q];
                    a01 = ffma2_(cc, w2.x, a01);
                    a23 = ffma2_(cc, w2.y, a23);
                }
                ((ulonglong2*)s->scratch4)[256 + sg * 64 + q0] = make_ulonglong2(a01, a23);
            }
        }
        __syncthreads();
        if (tid < 256) {           // reduce round A
            int q = tid >> 2, c = tid & 3;
            float v = bif[tid];
#pragma unroll
            for (int sg = 0; sg < 4; ++sg) v += sc[(sg * 64 + q) * 4 + c];
            s->z[tid] = v;
        } else if (tid < 471) {    // reduce round B (outputs 256..470)
            int j = tid;
            int q0 = (j >> 2) - 64, c = j & 3;
            float v = bif[j];
#pragma unroll
            for (int sg = 0; sg < 4; ++sg) v += sc[(256 + sg * 64 + q0) * 4 + c];
            s->z[j] = v;
        }
        __syncthreads();

        // P5: parse interface (norms parallelized across warps 8..12)
        if (tid < Rn) s->rstr[tid] = 1.0f + softp_(s->z[256 + tid]);
        if (tid >= 4 && tid < 8) s->freeg[tid - 4] = sigm_(s->z[453 + (tid - 4)]);
        if (tid == 8)  s->wstr   = 1.0f + softp_(s->z[324]);
        if (tid == 9)  s->allocg = sigm_(s->z[457]);
        if (tid == 10) s->writeg = sigm_(s->z[458]);
        if (tid >= 64 && tid < 128) {
            int w = tid - 64;
            s->er[w] = sigm_(s->z[325 + w]);
            s->wv[w] = s->z[389 + w];
        }
        if (warp >= 8 && warp < 12) {
            int r = warp - 8;
            float v1 = s->z[lane * 4 + r];
            float v2 = s->z[(lane + 32) * 4 + r];
            float s2 = fmaf(v1, v1, v2 * v2);
#pragma unroll
            for (int o = 16; o; o >>= 1) s2 += __shfl_xor_sync(0xffffffffu, s2, o);
            if (lane == 0) s->red[74 + r] = 1.0f / (sqrtf(s2) + EPSf);
        }
        if (warp == 12) {
            float v1 = s->z[260 + lane];
            float v2 = s->z[260 + lane + 32];
            float s2 = fmaf(v1, v1, v2 * v2);
#pragma unroll
            for (int o = 16; o; o >>= 1) s2 += __shfl_xor_sync(0xffffffffu, s2, o);
            if (lane == 0) s->red[78] = 1.0f / (sqrtf(s2) + EPSf);
        }
        if (tid >= 24 && tid < 28) {
            int r = tid - 24;
            float a = s->z[459 + r], bm = s->z[463 + r], c = s->z[467 + r];
            float mx = fmaxf(a, fmaxf(bm, c));
            float ea = expf(a - mx), eb = expf(bm - mx), ec = expf(c - mx);
            float si = 1.0f / (ea + eb + ec);
            s->modes[0][r] = ea * si; s->modes[1][r] = eb * si; s->modes[2][r] = ec * si;
        }
        __syncthreads();
        if (tid < 256)
            ((float*)s->keyn4)[tid] = s->z[tid] * s->red[74 + (tid & 3)] * s->rstr[tid & 3];
        if (tid < Wn) s->wkeyn[tid] = s->z[260 + tid] * s->red[78] * s->wstr;
        __syncthreads();

        // P6: retention + usage + write-content sim (old mem), pair split
        {
            int row = tid >> 1, ph = tid & 1;
            float nrm = 0.f, dot = 0.f;
            int w0 = ph * 32;
#pragma unroll 8
            for (int w = w0; w < w0 + 32; ++w) {
                float m = s->mem[row][w];
                nrm = fmaf(m, m, nrm);
                dot = fmaf(m, s->wkeyn[w], dot);
            }
            nrm += __shfl_xor_sync(0xffffffffu, nrm, 1);
            dot += __shfl_xor_sync(0xffffffffu, dot, 1);
            if (ph == 0) {
                float4 rw4 = s->rwv[row];
                float ret = (1.f - s->freeg[0] * rw4.x) * (1.f - s->freeg[1] * rw4.y) *
                            (1.f - s->freeg[2] * rw4.z) * (1.f - s->freeg[3] * rw4.w);
                float u = s->usage[row], w0v = s->ww[row];
                u = (u + w0v - u * w0v) * ret;
                s->usage[row] = u;
                s->skey[row] = ((unsigned long long)__float_as_uint(u) << 32) | (unsigned int)row;
                s->wc[row] = dot / (sqrtf(nrm) + EPSf);
            }
        }
        __syncthreads();
        {   // write-content softmax over n
            float v = (tid < 256) ? s->wc[tid] : -INFINITY;
            float mx = bmax(s->red, v, tid);
            float e = (tid < 256) ? expf(v - mx) : 0.f;
            float sm = bsum(s->red, e, tid);
            if (tid < 256) s->wc[tid] = e / sm;
        }
        __syncthreads();

        // P7: allocation — hybrid bitonic sort + warp-scan cumprod
        {
            unsigned long long key = (tid < 256) ? s->skey[tid] : 0xFFFFFFFFFFFFFFFFull;
            for (int k = 2; k <= 256; k <<= 1) {
                for (int j = k >> 1; j > 0; j >>= 1) {
                    bool up = ((tid & k) == 0);
                    bool keepmin = (((tid & j) == 0) == up);
                    if (j >= 32) {
                        if (tid < 256) s->skey[tid] = key;
                        __syncthreads();
                        if (tid < 256) {
                            unsigned long long other = s->skey[tid ^ j];
                            key = keepmin ? (key < other ? key : other)
                                          : (key < other ? other : key);
                        }
                        __syncthreads();
                    } else {
                        unsigned long long other = __shfl_xor_sync(0xffffffffu, key, j);
                        key = keepmin ? (key < other ? key : other)
                                      : (key < other ? other : key);
                    }
                }
            }
            float us = __uint_as_float((unsigned int)(key >> 32));
            float v = us;
#pragma unroll
            for (int o = 1; o < 32; o <<= 1) {
                float p = __shfl_up_sync(0xffffffffu, v, o);
                if (lane >= o) v *= p;
            }
            if (lane == 31 && tid < 256) s->red[warp] = v;
            __syncthreads();
            if (tid == 0) {
                float p = 1.0f;
#pragma unroll
                for (int w = 0; w < 8; ++w) { s->red[16 + w] = p; p *= s->red[w]; }
            }
            __syncthreads();
            if (tid < 256) {
                float wpre = s->red[16 + warp];
                v *= wpre;
                float p = __shfl_up_sync(0xffffffffu, v, 1);
                float excl = (lane == 0) ? wpre : p;
                unsigned int oi = (unsigned int)(key & 0xffffffffu);
                s->alloc_[oi] = (1.0f - us) * excl;
            }
        }
        __syncthreads();

        // P8: new write weights
        float wwsum;
        {
            float wwn = 0.f;
            if (tid < 256) {
                float ag = s->allocg;
                wwn = s->writeg * (ag * s->alloc_[tid] + (1.0f - ag) * s->wc[tid]);
                s->ww[tid] = wwn;
            }
            wwsum = bsum(s->red, wwn, tid);
        }
        __syncthreads();

        // P9: memory update + read-content sim, pair split, FFMA2 dots
        {
            int row = tid >> 1, ph = tid & 1;
            float wwn = s->ww[row];
            float nrm = 0.f;
            unsigned long long d01 = 0ull, d23 = 0ull;
            const ulonglong2* kk = (const ulonglong2*)s->keyn4;
            int w0 = ph * 32;
#pragma unroll 8
            for (int w = w0; w < w0 + 32; ++w) {
                float m = s->mem[row][w];
                float u2 = fmaf(wwn, s->wv[w], m);
                m = fmaf(-(wwn * s->er[w]), m, u2);
                s->mem[row][w] = m;
                nrm = fmaf(m, m, nrm);
                unsigned long long mm = pk2(m, m);
                ulonglong2 k2 = kk[w];
                d01 = ffma2_(mm, k2.x, d01);
                d23 = ffma2_(mm, k2.y, d23);
            }
            float d0, d1, d2, d3;
            up2(d01, d0, d1); up2(d23, d2, d3);
            nrm += __shfl_xor_sync(0xffffffffu, nrm, 1);
            d0 += __shfl_xor_sync(0xffffffffu, d0, 1);
            d1 += __shfl_xor_sync(0xffffffffu, d1, 1);
            d2 += __shfl_xor_sync(0xffffffffu, d2, 1);
            d3 += __shfl_xor_sync(0xffffffffu, d3, 1);
            if (ph == 0) {
                float inv = 1.0f / (sqrtf(nrm) + EPSf);
                s->rcv[row] = make_float4(d0 * inv, d1 * inv, d2 * inv, d3 * inv);
            }
        }
        __syncthreads();
        {   // read-content softmax over n, per r
            float v[4];
            if (tid < 256) {
                float4 rv = s->rcv[tid];
                v[0] = rv.x; v[1] = rv.y; v[2] = rv.z; v[3] = rv.w;
            } else {
                v[0] = v[1] = v[2] = v[3] = -INFINITY;
            }
            float m4[4] = {v[0], v[1], v[2], v[3]};
            bred4(s->red, m4, tid, 1);
#pragma unroll
            for (int r = 0; r < 4; ++r) v[r] = (tid < 256) ? expf(v[r] - m4[r]) : 0.f;
            float s4[4] = {v[0], v[1], v[2], v[3]};
            bred4(s->red, s4, tid, 0);
            if (tid < 256)
                s->rcv[tid] = make_float4(v[0] / s4[0], v[1] / s4[1], v[2] / s4[2], v[3] / s4[3]);
        }
        __syncthreads();

        // P10: link update + bwd + fwd for THIS CTA's 128 rows, FFMA2 accum.
        {
            int col = tid & 255, sub = tid >> 8;
            float wwn = s->ww[col], prn = s->prec[col];
            unsigned long long b01 = 0ull, b23 = 0ull;
            for (int ts = 0; ts < 2; ++ts) {
                int m0 = hfbase + ts * 64 + sub * 32;
                float* lb = (float*)s->Lst[sub];
#pragma unroll 8
                for (int ml = 0; ml < 32; ++ml) {
                    int m = m0 + ml;
                    float L = lk[m * Nn + col];
                    float wm = s->ww[m];
                    float Ln = fmaf(wm, prn, L);
                    Ln = fmaf(-(wm + wwn), L, Ln);
                    if (m == col) Ln = 0.f;
                    lk[m * Nn + col] = Ln;
                    lb[ml * 260 + col] = Ln;
                    unsigned long long LL = pk2(Ln, Ln);
                    ulonglong2 rr = rw2[m];
                    b01 = ffma2_(LL, rr.x, b01);
                    b23 = ffma2_(LL, rr.y, b23);
                }
                __syncthreads();
                {   // fwd partials for the 64 rows of this tile-step, FFMA2
                    int fsub = tid >> 8, seg = (tid >> 5) & 7, rloc = tid & 31;
                    const float4* Lb4 = s->Lst[fsub];
                    unsigned long long a01 = 0ull, a23 = 0ull;
#pragma unroll
                    for (int k4 = 0; k4 < 8; ++k4) {
                        float4 L4 = Lb4[rloc * 65 + seg * 8 + k4];
                        int c0 = (seg * 8 + k4) * 4;
                        ulonglong2 ra = rw2[c0], rb = rw2[c0 + 1];
                        ulonglong2 rc_ = rw2[c0 + 2], rd = rw2[c0 + 3];
                        unsigned long long lx = pk2(L4.x, L4.x);
                        unsigned long long ly = pk2(L4.y, L4.y);
                        unsigned long long lz = pk2(L4.z, L4.z);
                        unsigned long long lw = pk2(L4.w, L4.w);
                        a01 = ffma2_(lx, ra.x, a01); a23 = ffma2_(lx, ra.y, a23);
                        a01 = ffma2_(ly, rb.x, a01); a23 = ffma2_(ly, rb.y, a23);
                        a01 = ffma2_(lz, rc_.x, a01); a23 = ffma2_(lz, rc_.y, a23);
                        a01 = ffma2_(lw, rd.x, a01); a23 = ffma2_(lw, rd.y, a23);
                    }
                    ((ulonglong2*)s->scratch4)[fsub * 256 + rloc * 8 + seg] =
                        make_ulonglong2(a01, a23);
                }
                __syncthreads();
                if (tid < 256) {   // reduce 8 segs -> fwd rows of this tile-step
                    int row = tid >> 2, r = tid & 3;           // row 0..63
                    int fsub = row >> 5, rloc = row & 31;
                    float v = 0.f;
#pragma unroll
                    for (int seg = 0; seg < 8; ++seg)
                        v += sc[(fsub * 256 + rloc * 8 + seg) * 4 + r];
                    ((float*)s->fwdv)[(hfbase + ts * 64 + row) * 4 + r] = v;
                }
                // next ts's post-column barrier protects scratch reuse
            }
            __syncthreads();
            ((ulonglong2*)s->scratch4)[tid] = make_ulonglong2(b01, b23);
            __syncthreads();
            int buf = t & 1;
            if (tid < 256) {       // merge sub halves of bwd partial, publish
                float4 pa = s->scratch4[tid], pb = s->scratch4[tid + 256];
                float4 bw = make_float4(pa.x + pb.x, pa.y + pb.y, pa.z + pb.z, pa.w + pb.w);
                s->bwdv[tid] = bw;
                __stcg(&g_xch[b][buf][hf][tid], bw);
            }
            if (tid >= 256 && tid < 384) {   // publish fwd half
                int row = tid - 256;
                __stcg(&g_xch[b][buf][hf][256 + row], s->fwdv[hfbase + row]);
            }
            if (tid < 256)
                s->prec[tid] = fmaf(1.0f - wwsum, s->prec[tid], s->ww[tid]);
            __threadfence();
            asm volatile("barrier.cluster.arrive.aligned;" ::: "memory");
            asm volatile("barrier.cluster.wait.aligned;" ::: "memory");
            int ph = hf ^ 1;
            if (tid < 256) {       // combine peer bwd partial
                float4 pb = __ldcg(&g_xch[b][buf][ph][tid]);
                float4 bw = s->bwdv[tid];
                s->bwdv[tid] = make_float4(bw.x + pb.x, bw.y + pb.y, bw.z + pb.z, bw.w + pb.w);
            }
            if (tid >= 256 && tid < 384) {   // fetch peer fwd half
                int row = tid - 256;
                s->fwdv[ph * 128 + row] = __ldcg(&g_xch[b][buf][ph][256 + row]);
            }
        }
        __syncthreads();

        // P12: new read weights
        if (tid < 256) {
            float4 bw = s->bwdv[tid], rc4 = s->rcv[tid], fw = s->fwdv[tid];
            float4 nrw;
            nrw.x = bw.x * s->modes[0][0] + rc4.x * s->modes[1][0] + fw.x * s->modes[2][0];
            nrw.y = bw.y * s->modes[0][1] + rc4.y * s->modes[1][1] + fw.y * s->modes[2][1];
            nrw.z = bw.z * s->modes[0][2] + rc4.z * s->modes[1][2] + fw.z * s->modes[2][2];
            nrw.w = bw.w * s->modes[0][3] + rc4.w * s->modes[1][3] + fw.w * s->modes[2][3];
            s->rwv[tid] = nrw;
        }
        __syncthreads();

        // P13: rvec[w][r] = sum_n mem[n][w] * rw[n][r], FFMA2
        {
            int w = tid & 63, seg = tid >> 6;
            unsigned long long a01 = 0ull, a23 = 0ull;
            int n0 = seg * 32;
#pragma unroll 8
            for (int n = n0; n < n0 + 32; ++n) {
                float m = s->mem[n][w];
                unsigned long long mm = pk2(m, m);
                ulonglong2 rr = rw2[n];
                a01 = ffma2_(mm, rr.x, a01);
                a23 = ffma2_(mm, rr.y, a23);
            }
            ((ulonglong2*)s->scratch4)[tid] = make_ulonglong2(a01, a23);
        }
        __syncthreads();
        if (tid < 256) {
            int w = tid >> 2, r = tid & 3;
            float v = 0.f;
#pragma unroll
            for (int seg = 0; seg < 8; ++seg) v += sc[(seg * 64 + w) * 4 + r];
            s->rvec[w * 4 + r] = v;
        }
        __syncthreads();

        // P14: out = nn @ W_out + rvec @ W_mem_out  (8 segments of 32 j)
        {
            int o = tid & 63, seg = tid >> 6;
            float acc = 0.f;
            int j0 = seg * 32;
#pragma unroll 8
            for (int j = j0; j < j0 + 32; ++j) {
                acc = fmaf(s->nn[j], Wout[j * 64 + o], acc);
                acc = fmaf(s->rvec[j], Wmem[j * 64 + o], acc);
            }
            sc[seg * 64 + o] = acc;
        }
        __syncthreads();
        if (hf == 0 && tid < 64) {
            float v = 0.f;
#pragma unroll
            for (int seg = 0; seg < 8; ++seg) v += sc[seg * 64 + tid];
            out[(t * Bn + b) * 64 + tid] = v;
        }
        __syncthreads();
    }
}

extern "C" void kernel_launch(void* const* d_in, const int* in_sizes, int n_in,
                              void* d_out, int out_size) {
    (void)in_sizes; (void)n_in; (void)out_size;
    const float* x    = (const float*)d_in[0];
    const float* W1   = (const float*)d_in[1];
    const float* b1   = (const float*)d_in[2];
    const float* W2   = (const float*)d_in[3];
    const float* b2   = (const float*)d_in[4];
    const float* Wif  = (const float*)d_in[5];
    const float* bif  = (const float*)d_in[6];
    const float* Wout = (const float*)d_in[7];
    const float* Wmem = (const float*)d_in[8];
    float* out = (float*)d_out;

    cudaFuncSetAttribute(dnc_kernel, cudaFuncAttributeMaxDynamicSharedMemorySize,
                         (int)sizeof(SMem));
    repack_kernel<<<256, IFP>>>(Wif);

    cudaLaunchConfig_t cfg = {};
    cfg.gridDim = dim3(Bn * 2, 1, 1);
    cfg.blockDim = dim3(NT, 1, 1);
    cfg.dynamicSmemBytes = sizeof(SMem);
    cudaLaunchAttribute attrs[1];
    attrs[0].id = cudaLaunchAttributeClusterDimension;
    attrs[0].val.clusterDim.x = 2;
    attrs[0].val.clusterDim.y = 1;
    attrs[0].val.clusterDim.z = 1;
    cfg.attrs = attrs;
    cfg.numAttrs = 1;
    cudaLaunchKernelEx(&cfg, dnc_kernel, x, W1, b1, W2, b2, bif, Wout, Wmem, out);
}

// round 17
// speedup vs baseline: 1.5711x; 1.5711x over previous
#include <cuda_runtime.h>
#include <math.h>

#define Tn   64
#define Bn   16
#define Nn   256
#define Wn   64
#define Rn   4
#define INn  64
#define IFS  471
#define IFP  472
#define EPSf 1e-6f
#define NT   512

// global scratch (allocation-free)
__device__ float g_link[Bn * Nn * Nn];   // 4 MB, L2-resident; lk[row*256+col]
__device__ float g_Wifp[256 * IFP];      // W_if repacked pitch 471 -> 472
// exchange mailbox: [batch][buf][cta]: [0..255]=bwd partial, [256..383]=fwd half
__device__ float4 g_xch[Bn][2][2][384];

struct SMem {
    float  mem[Nn][Wn + 1];          // pitch 65, conflict-free
    float4 Lst[2][32 * 65];          // staging tiles (two 32-row groups)
    float4 scratch4[512];
    float4 fwdv[Nn];
    float4 bwdv[Nn];
    float4 rcv[Nn];
    float4 rwv[Nn];
    float4 keyn4[Wn];
    float  rvec[256];
    float  ctrl[INn + 256];
    float  h[256];
    float  nn[256];
    float  z[IFP];
    float  ww[Nn];
    float  prec[Nn];
    float  usage[Nn];
    float  alloc_[Nn];
    unsigned long long skey[Nn];
    float  wkeyn[Wn];
    float  er[Wn];
    float  wv[Wn];
    float  wc[Nn];
    float  red[80];
    float  rstr[Rn];
    float  freeg[Rn];
    float  modes[3][Rn];
    float  wstr, allocg, writeg;
};

__device__ __forceinline__ float sigm_(float x) { return 1.0f / (1.0f + expf(-x)); }
__device__ __forceinline__ float softp_(float x) { return fmaxf(x, 0.0f) + log1pf(expf(-fabsf(x))); }

// block reductions for 16 warps
__device__ __forceinline__ float bsum(float* red, float v, int tid) {
#pragma unroll
    for (int o = 16; o; o >>= 1) v += __shfl_xor_sync(0xffffffffu, v, o);
    if ((tid & 31) == 0) red[tid >> 5] = v;
    __syncthreads();
    if (tid == 0) {
        float a = red[0];
#pragma unroll
        for (int i = 1; i < 16; ++i) a += red[i];
        red[72] = a;
    }
    __syncthreads();
    return red[72];
}
__device__ __forceinline__ float bmax(float* red, float v, int tid) {
#pragma unroll
    for (int o = 16; o; o >>= 1) v = fmaxf(v, __shfl_xor_sync(0xffffffffu, v, o));
    if ((tid & 31) == 0) red[tid >> 5] = v;
    __syncthreads();
    if (tid == 0) {
        float a = red[0];
#pragma unroll
        for (int i = 1; i < 16; ++i) a = fmaxf(a, red[i]);
        red[72] = a;
    }
    __syncthreads();
    return red[72];
}
__device__ __forceinline__ void bred4(float* red, float* v, int tid, int domax) {
#pragma unroll
    for (int o = 16; o; o >>= 1) {
#pragma unroll
        for (int r = 0; r < 4; ++r) {
            float w = __shfl_xor_sync(0xffffffffu, v[r], o);
            v[r] = domax ? fmaxf(v[r], w) : (v[r] + w);
        }
    }
    if ((tid & 31) == 0) {
#pragma unroll
        for (int r = 0; r < 4; ++r) red[(tid >> 5) * 4 + r] = v[r];
    }
    __syncthreads();
    if (tid < 4) {
        float a = red[tid];
#pragma unroll
        for (int w = 1; w < 16; ++w) {
            float b = red[w * 4 + tid];
            a = domax ? fmaxf(a, b) : (a + b);
        }
        red[64 + tid] = a;
    }
    __syncthreads();
#pragma unroll
    for (int r = 0; r < 4; ++r) v[r] = red[64 + r];
}

__global__ void repack_kernel(const float* __restrict__ Wif) {
    int i = blockIdx.x;
    int j = threadIdx.x;
    if (j < IFP) g_Wifp[i * IFP + j] = (j < IFS) ? Wif[i * IFS + j] : 0.0f;
}

__global__ void __launch_bounds__(NT, 1) __cluster_dims__(2, 1, 1)
dnc_kernel(const float* __restrict__ x, const float* __restrict__ W1,
           const float* __restrict__ b1, const float* __restrict__ W2,
           const float* __restrict__ b2, const float* __restrict__ bif,
           const float* __restrict__ Wout, const float* __restrict__ Wmem,
           float* __restrict__ out) {
    extern __shared__ char smraw[];
    SMem* s = (SMem*)smraw;
    const int tid = threadIdx.x;
    const int lane = tid & 31, warp = tid >> 5;
    const int b = blockIdx.x >> 1;     // batch
    const int hf = blockIdx.x & 1;     // link row half owned by this CTA
    const int hfbase = hf * 128;
    float* lk = g_link + b * (Nn * Nn);

    // init carries (each CTA zeros its own link half; small state duplicated)
    {
        float4 z4 = make_float4(0.f, 0.f, 0.f, 0.f);
        float4* lk4 = (float4*)(lk + hfbase * Nn);
        for (int i = tid; i < 128 * Nn / 4; i += NT) lk4[i] = z4;
        if (tid < 256) {
#pragma unroll 8
            for (int w = 0; w < Wn; ++w) s->mem[tid][w] = EPSf;
            s->usage[tid] = 0.0f;
            s->ww[tid] = 0.0f;
            s->prec[tid] = 0.0f;
            s->rwv[tid] = z4;
            s->rvec[tid] = 0.0f;
        }
    }
    __syncthreads();

    float* sc = (float*)s->scratch4;

    for (int t = 0; t < Tn; ++t) {
        // P1: controller input
        if (tid < INn) s->ctrl[tid] = x[(t * Bn + b) * INn + tid];
        if (tid < 256) s->ctrl[INn + tid] = s->rvec[tid];
        __syncthreads();

        // P2: h = tanh(ctrl @ W1 + b1), 320x256 (8 segments of 40)
        {
            int sg = tid >> 6, q = tid & 63;
            const float4* Wp = (const float4*)W1;
            float4 acc = make_float4(0.f, 0.f, 0.f, 0.f);
            int i0 = sg * 40;
#pragma unroll 8
            for (int i = i0; i < i0 + 40; ++i) {
                float c = s->ctrl[i];
                float4 w4 = Wp[i * 64 + q];
                acc.x = fmaf(c, w4.x, acc.x); acc.y = fmaf(c, w4.y, acc.y);
                acc.z = fmaf(c, w4.z, acc.z); acc.w = fmaf(c, w4.w, acc.w);
            }
            s->scratch4[sg * 64 + q] = acc;
        }
        __syncthreads();
        if (tid < 256) {
            int q = tid >> 2, c = tid & 3;
            float v = b1[tid];
#pragma unroll
            for (int sg = 0; sg < 8; ++sg) v += sc[(sg * 64 + q) * 4 + c];
            s->h[tid] = tanhf(v);
        }
        __syncthreads();

        // P3: nn = tanh(h @ W2 + b2), 256x256 (8 segments of 32)
        {
            int sg = tid >> 6, q = tid & 63;
            const float4* Wp = (const float4*)W2;
            float4 acc = make_float4(0.f, 0.f, 0.f, 0.f);
            int i0 = sg * 32;
#pragma unroll 8
            for (int i = i0; i < i0 + 32; ++i) {
                float c = s->h[i];
                float4 w4 = Wp[i * 64 + q];
                acc.x = fmaf(c, w4.x, acc.x); acc.y = fmaf(c, w4.y, acc.y);
                acc.z = fmaf(c, w4.z, acc.z); acc.w = fmaf(c, w4.w, acc.w);
            }
            s->scratch4[sg * 64 + q] = acc;
        }
        __syncthreads();
        if (tid < 256) {
            int q = tid >> 2, c = tid & 3;
            float v = b2[tid];
#pragma unroll
            for (int sg = 0; sg < 8; ++sg) v += sc[(sg * 64 + q) * 4 + c];
            s->nn[tid] = tanhf(v);
        }
        __syncthreads();

        // P4 FUSED: z = nn @ W_if + b_if, rounds A and B run concurrently.
        if (tid < 256) {
            int sg = tid >> 6, q = tid & 63;
            const float4* Wp = (const float4*)g_Wifp;
            float4 acc = make_float4(0.f, 0.f, 0.f, 0.f);
            int i0 = sg * 64;
#pragma unroll 8
            for (int i = i0; i < i0 + 64; ++i) {
                float c = s->nn[i];
                float4 w4 = Wp[i * 118 + q];
                acc.x = fmaf(c, w4.x, acc.x); acc.y = fmaf(c, w4.y, acc.y);
                acc.z = fmaf(c, w4.z, acc.z); acc.w = fmaf(c, w4.w, acc.w);
            }
            s->scratch4[sg * 64 + q] = acc;
        } else {
            int tid2 = tid - 256;
            int sg = tid2 >> 6, q0 = tid2 & 63;
            if (q0 < 54) {
                const float4* Wp = (const float4*)g_Wifp;
                float4 acc = make_float4(0.f, 0.f, 0.f, 0.f);
                int i0 = sg * 64, q = 64 + q0;
#pragma unroll 8
                for (int i = i0; i < i0 + 64; ++i) {
                    float c = s->nn[i];
                    float4 w4 = Wp[i * 118 + q];
                    acc.x = fmaf(c, w4.x, acc.x); acc.y = fmaf(c, w4.y, acc.y);
                    acc.z = fmaf(c, w4.z, acc.z); acc.w = fmaf(c, w4.w, acc.w);
                }
                s->scratch4[256 + sg * 64 + q0] = acc;
            }
        }
        __syncthreads();
        if (tid < 256) {           // reduce round A
            int q = tid >> 2, c = tid & 3;
            float v = bif[tid];
#pragma unroll
            for (int sg = 0; sg < 4; ++sg) v += sc[(sg * 64 + q) * 4 + c];
            s->z[tid] = v;
        } else if (tid < 471) {    // reduce round B (outputs 256..470)
            int j = tid;
            int q0 = (j >> 2) - 64, c = j & 3;
            float v = bif[j];
#pragma unroll
            for (int sg = 0; sg < 4; ++sg) v += sc[(256 + sg * 64 + q0) * 4 + c];
            s->z[j] = v;
        }
        __syncthreads();

        // P5: parse interface (norms parallelized across warps 8..12)
        if (tid < Rn) s->rstr[tid] = 1.0f + softp_(s->z[256 + tid]);
        if (tid >= 4 && tid < 8) s->freeg[tid - 4] = sigm_(s->z[453 + (tid - 4)]);
        if (tid == 8)  s->wstr   = 1.0f + softp_(s->z[324]);
        if (tid == 9)  s->allocg = sigm_(s->z[457]);
        if (tid == 10) s->writeg = sigm_(s->z[458]);
        if (tid >= 64 && tid < 128) {
            int w = tid - 64;
            s->er[w] = sigm_(s->z[325 + w]);
            s->wv[w] = s->z[389 + w];
        }
        if (warp >= 8 && warp < 12) {   // read key inverse norms, one warp per r
            int r = warp - 8;
            float v1 = s->z[lane * 4 + r];
            float v2 = s->z[(lane + 32) * 4 + r];
            float s2 = fmaf(v1, v1, v2 * v2);
#pragma unroll
            for (int o = 16; o; o >>= 1) s2 += __shfl_xor_sync(0xffffffffu, s2, o);
            if (lane == 0) s->red[74 + r] = 1.0f / (sqrtf(s2) + EPSf);
        }
        if (warp == 12) {               // write key inverse norm
            float v1 = s->z[260 + lane];
            float v2 = s->z[260 + lane + 32];
            float s2 = fmaf(v1, v1, v2 * v2);
#pragma unroll
            for (int o = 16; o; o >>= 1) s2 += __shfl_xor_sync(0xffffffffu, s2, o);
            if (lane == 0) s->red[78] = 1.0f / (sqrtf(s2) + EPSf);
        }
        if (tid >= 24 && tid < 28) {    // read-mode softmax over 3
            int r = tid - 24;
            float a = s->z[459 + r], bm = s->z[463 + r], c = s->z[467 + r];
            float mx = fmaxf(a, fmaxf(bm, c));
            float ea = expf(a - mx), eb = expf(bm - mx), ec = expf(c - mx);
            float si = 1.0f / (ea + eb + ec);
            s->modes[0][r] = ea * si; s->modes[1][r] = eb * si; s->modes[2][r] = ec * si;
        }
        __syncthreads();
        if (tid < 256)
            ((float*)s->keyn4)[tid] = s->z[tid] * s->red[74 + (tid & 3)] * s->rstr[tid & 3];
        if (tid < Wn) s->wkeyn[tid] = s->z[260 + tid] * s->red[78] * s->wstr;
        __syncthreads();

        // P6: retention + usage (old ww/rw) + write-content sim (old mem), pair split
        {
            int row = tid >> 1, ph = tid & 1;
            float nrm = 0.f, dot = 0.f;
            int w0 = ph * 32;
#pragma unroll 8
            for (int w = w0; w < w0 + 32; ++w) {
                float m = s->mem[row][w];
                nrm = fmaf(m, m, nrm);
                dot = fmaf(m, s->wkeyn[w], dot);
            }
            nrm += __shfl_xor_sync(0xffffffffu, nrm, 1);
            dot += __shfl_xor_sync(0xffffffffu, dot, 1);
            if (ph == 0) {
                float4 rw4 = s->rwv[row];
                float ret = (1.f - s->freeg[0] * rw4.x) * (1.f - s->freeg[1] * rw4.y) *
                            (1.f - s->freeg[2] * rw4.z) * (1.f - s->freeg[3] * rw4.w);
                float u = s->usage[row], w0v = s->ww[row];
                u = (u + w0v - u * w0v) * ret;
                s->usage[row] = u;
                s->skey[row] = ((unsigned long long)__float_as_uint(u) << 32) | (unsigned int)row;
                s->wc[row] = dot / (sqrtf(nrm) + EPSf);
            }
        }
        __syncthreads();
        {   // write-content softmax over n
            float v = (tid < 256) ? s->wc[tid] : -INFINITY;
            float mx = bmax(s->red, v, tid);
            float e = (tid < 256) ? expf(v - mx) : 0.f;
            float sm = bsum(s->red, e, tid);
            if (tid < 256) s->wc[tid] = e / sm;
        }
        __syncthreads();

        // P7: allocation — hybrid bitonic sort + warp-scan cumprod
        {
            unsigned long long key = (tid < 256) ? s->skey[tid] : 0xFFFFFFFFFFFFFFFFull;
            for (int k = 2; k <= 256; k <<= 1) {
                for (int j = k >> 1; j > 0; j >>= 1) {
                    bool up = ((tid & k) == 0);
                    bool keepmin = (((tid & j) == 0) == up);
                    if (j >= 32) {
                        if (tid < 256) s->skey[tid] = key;
                        __syncthreads();
                        if (tid < 256) {
                            unsigned long long other = s->skey[tid ^ j];
                            key = keepmin ? (key < other ? key : other)
                                          : (key < other ? other : key);
                        }
                        __syncthreads();
                    } else {
                        unsigned long long other = __shfl_xor_sync(0xffffffffu, key, j);
                        key = keepmin ? (key < other ? key : other)
                                      : (key < other ? other : key);
                    }
                }
            }
            float us = __uint_as_float((unsigned int)(key >> 32));
            float v = us;
#pragma unroll
            for (int o = 1; o < 32; o <<= 1) {
                float p = __shfl_up_sync(0xffffffffu, v, o);
                if (lane >= o) v *= p;
            }
            if (lane == 31 && tid < 256) s->red[warp] = v;
            __syncthreads();
            if (tid == 0) {
                float p = 1.0f;
#pragma unroll
                for (int w = 0; w < 8; ++w) { s->red[16 + w] = p; p *= s->red[w]; }
            }
            __syncthreads();
            if (tid < 256) {
                float wpre = s->red[16 + warp];
                v *= wpre;
                float p = __shfl_up_sync(0xffffffffu, v, 1);
                float excl = (lane == 0) ? wpre : p;
                unsigned int oi = (unsigned int)(key & 0xffffffffu);
                s->alloc_[oi] = (1.0f - us) * excl;
            }
        }
        __syncthreads();

        // P8: new write weights
        float wwsum;
        {
            float wwn = 0.f;
            if (tid < 256) {
                float ag = s->allocg;
                wwn = s->writeg * (ag * s->alloc_[tid] + (1.0f - ag) * s->wc[tid]);
                s->ww[tid] = wwn;
            }
            wwsum = bsum(s->red, wwn, tid);
        }
        __syncthreads();

        // P9: memory update + read-content sim on new mem, pair split
        {
            int row = tid >> 1, ph = tid & 1;
            float wwn = s->ww[row];
            float nrm = 0.f, d0 = 0.f, d1 = 0.f, d2 = 0.f, d3 = 0.f;
            int w0 = ph * 32;
#pragma unroll 8
            for (int w = w0; w < w0 + 32; ++w) {
                float m = s->mem[row][w];
                float u2 = fmaf(wwn, s->wv[w], m);
                m = fmaf(-(wwn * s->er[w]), m, u2);
                s->mem[row][w] = m;
                nrm = fmaf(m, m, nrm);
                float4 k4 = s->keyn4[w];
                d0 = fmaf(m, k4.x, d0); d1 = fmaf(m, k4.y, d1);
                d2 = fmaf(m, k4.z, d2); d3 = fmaf(m, k4.w, d3);
            }
            nrm += __shfl_xor_sync(0xffffffffu, nrm, 1);
            d0 += __shfl_xor_sync(0xffffffffu, d0, 1);
            d1 += __shfl_xor_sync(0xffffffffu, d1, 1);
            d2 += __shfl_xor_sync(0xffffffffu, d2, 1);
            d3 += __shfl_xor_sync(0xffffffffu, d3, 1);
            if (ph == 0) {
                float inv = 1.0f / (sqrtf(nrm) + EPSf);
                s->rcv[row] = make_float4(d0 * inv, d1 * inv, d2 * inv, d3 * inv);
            }
        }
        __syncthreads();
        {   // read-content softmax over n, per r
            float v[4];
            if (tid < 256) {
                float4 rv = s->rcv[tid];
                v[0] = rv.x; v[1] = rv.y; v[2] = rv.z; v[3] = rv.w;
            } else {
                v[0] = v[1] = v[2] = v[3] = -INFINITY;
            }
            float m4[4] = {v[0], v[1], v[2], v[3]};
            bred4(s->red, m4, tid, 1);
#pragma unroll
            for (int r = 0; r < 4; ++r) v[r] = (tid < 256) ? expf(v[r] - m4[r]) : 0.f;
            float s4[4] = {v[0], v[1], v[2], v[3]};
            bred4(s->red, s4, tid, 0);
            if (tid < 256)
                s->rcv[tid] = make_float4(v[0] / s4[0], v[1] / s4[1], v[2] / s4[2], v[3] / s4[3]);
        }
        __syncthreads();

        // P10: link update + bwd + fwd for THIS CTA's 128 rows only.
        {
            int col = tid & 255, sub = tid >> 8;
            float wwn = s->ww[col], prn = s->prec[col];
            float b0 = 0.f, b1a = 0.f, b2a = 0.f, b3 = 0.f;
            for (int ts = 0; ts < 2; ++ts) {
                int m0 = hfbase + ts * 64 + sub * 32;
                float* lb = (float*)s->Lst[sub];
#pragma unroll 8
                for (int ml = 0; ml < 32; ++ml) {
                    int m = m0 + ml;
                    float L = lk[m * Nn + col];
                    float wm = s->ww[m];
                    float Ln = fmaf(wm, prn, L);
                    Ln = fmaf(-(wm + wwn), L, Ln);
                    if (m == col) Ln = 0.f;
                    lk[m * Nn + col] = Ln;
                    lb[ml * 260 + col] = Ln;
                    float4 r4 = s->rwv[m];
                    b0 = fmaf(Ln, r4.x, b0); b1a = fmaf(Ln, r4.y, b1a);
                    b2a = fmaf(Ln, r4.z, b2a); b3 = fmaf(Ln, r4.w, b3);
                }
                __syncthreads();
                {   // fwd partials for the 64 rows of this tile-step
                    int fsub = tid >> 8, seg = (tid >> 5) & 7, rloc = tid & 31;
                    const float4* Lb4 = s->Lst[fsub];
                    float a0 = 0.f, a1 = 0.f, a2 = 0.f, a3 = 0.f;
#pragma unroll
                    for (int k4 = 0; k4 < 8; ++k4) {
                        float4 L4 = Lb4[rloc * 65 + seg * 8 + k4];
                        int c0 = (seg * 8 + k4) * 4;
                        float4 ra = s->rwv[c0], rb = s->rwv[c0 + 1];
                        float4 rc_ = s->rwv[c0 + 2], rd = s->rwv[c0 + 3];
                        a0 = fmaf(L4.x, ra.x, a0); a1 = fmaf(L4.x, ra.y, a1);
                        a2 = fmaf(L4.x, ra.z, a2); a3 = fmaf(L4.x, ra.w, a3);
                        a0 = fmaf(L4.y, rb.x, a0); a1 = fmaf(L4.y, rb.y, a1);
                        a2 = fmaf(L4.y, rb.z, a2); a3 = fmaf(L4.y, rb.w, a3);
                        a0 = fmaf(L4.z, rc_.x, a0); a1 = fmaf(L4.z, rc_.y, a1);
                        a2 = fmaf(L4.z, rc_.z, a2); a3 = fmaf(L4.z, rc_.w, a3);
                        a0 = fmaf(L4.w, rd.x, a0); a1 = fmaf(L4.w, rd.y, a1);
                        a2 = fmaf(L4.w, rd.z, a2); a3 = fmaf(L4.w, rd.w, a3);
                    }
                    s->scratch4[fsub * 256 + rloc * 8 + seg] = make_float4(a0, a1, a2, a3);
                }
                __syncthreads();
                if (tid < 256) {   // reduce 8 segs -> fwd rows of this tile-step
                    int row = tid >> 2, r = tid & 3;           // row 0..63
                    int fsub = row >> 5, rloc = row & 31;
                    float v = 0.f;
#pragma unroll
                    for (int seg = 0; seg < 8; ++seg)
                        v += sc[(fsub * 256 + rloc * 8 + seg) * 4 + r];
                    ((float*)s->fwdv)[(hfbase + ts * 64 + row) * 4 + r] = v;
                }
                // next ts's post-column barrier protects scratch reuse
            }
            __syncthreads();
            s->scratch4[tid] = make_float4(b0, b1a, b2a, b3);
            __syncthreads();
            int buf = t & 1;
            if (tid < 256) {       // merge sub halves of bwd partial, publish
                float4 pa = s->scratch4[tid], pb = s->scratch4[tid + 256];
                float4 bw = make_float4(pa.x + pb.x, pa.y + pb.y, pa.z + pb.z, pa.w + pb.w);
                s->bwdv[tid] = bw;
                __stcg(&g_xch[b][buf][hf][tid], bw);
            }
            if (tid >= 256 && tid < 384) {   // publish fwd half
                int row = tid - 256;
                __stcg(&g_xch[b][buf][hf][256 + row], s->fwdv[hfbase + row]);
            }
            if (tid < 256)
                s->prec[tid] = fmaf(1.0f - wwsum, s->prec[tid], s->ww[tid]);
            __threadfence();
            asm volatile("barrier.cluster.arrive.aligned;" ::: "memory");
            asm volatile("barrier.cluster.wait.aligned;" ::: "memory");
            int ph = hf ^ 1;
            if (tid < 256) {       // combine peer bwd partial
                float4 pb = __ldcg(&g_xch[b][buf][ph][tid]);
                float4 bw = s->bwdv[tid];
                s->bwdv[tid] = make_float4(bw.x + pb.x, bw.y + pb.y, bw.z + pb.z, bw.w + pb.w);
            }
            if (tid >= 256 && tid < 384) {   // fetch peer fwd half
                int row = tid - 256;
                s->fwdv[ph * 128 + row] = __ldcg(&g_xch[b][buf][ph][256 + row]);
            }
        }
        __syncthreads();

        // P12: new read weights
        if (tid < 256) {
            float4 bw = s->bwdv[tid], rc4 = s->rcv[tid], fw = s->fwdv[tid];
            float4 nrw;
            nrw.x = bw.x * s->modes[0][0] + rc4.x * s->modes[1][0] + fw.x * s->modes[2][0];
            nrw.y = bw.y * s->modes[0][1] + rc4.y * s->modes[1][1] + fw.y * s->modes[2][1];
            nrw.z = bw.z * s->modes[0][2] + rc4.z * s->modes[1][2] + fw.z * s->modes[2][2];
            nrw.w = bw.w * s->modes[0][3] + rc4.w * s->modes[1][3] + fw.w * s->modes[2][3];
            s->rwv[tid] = nrw;
        }
        __syncthreads();

        // P13: rvec[w][r] = sum_n mem[n][w] * rw[n][r]  (8 segments of 32 n)
        {
            int w = tid & 63, seg = tid >> 6;
            float a0 = 0.f, a1 = 0.f, a2 = 0.f, a3 = 0.f;
            int n0 = seg * 32;
#pragma unroll 8
            for (int n = n0; n < n0 + 32; ++n) {
                float m = s->mem[n][w];
                float4 r4 = s->rwv[n];
                a0 = fmaf(m, r4.x, a0); a1 = fmaf(m, r4.y, a1);
                a2 = fmaf(m, r4.z, a2); a3 = fmaf(m, r4.w, a3);
            }
            s->scratch4[tid] = make_float4(a0, a1, a2, a3);
        }
        __syncthreads();
        if (tid < 256) {
            int w = tid >> 2, r = tid & 3;
            float v = 0.f;
#pragma unroll
            for (int seg = 0; seg < 8; ++seg) v += sc[(seg * 64 + w) * 4 + r];
            s->rvec[w * 4 + r] = v;
        }
        __syncthreads();

        // P14 SPLIT: each CTA computes its own 32 of 64 output columns.
        // o = (tid&31) + hf*32; 16 segments of 16 j each.
        {
            int o = (tid & 31) + hf * 32;
            int seg = tid >> 5;             // 0..15
            float acc = 0.f;
            int j0 = seg * 16;
#pragma unroll 8
            for (int j = j0; j < j0 + 16; ++j) {
                acc = fmaf(s->nn[j], Wout[j * 64 + o], acc);
                acc = fmaf(s->rvec[j], Wmem[j * 64 + o], acc);
            }
            sc[seg * 32 + (tid & 31)] = acc;
        }
        __syncthreads();
        if (tid < 32) {
            float v = 0.f;
#pragma unroll
            for (int seg = 0; seg < 16; ++seg) v += sc[seg * 32 + tid];
            out[(t * Bn + b) * 64 + hf * 32 + tid] = v;
        }
        __syncthreads();
    }
}

extern "C" void kernel_launch(void* const* d_in, const int* in_sizes, int n_in,
                              void* d_out, int out_size) {
    (void)in_sizes; (void)n_in; (void)out_size;
    const float* x    = (const float*)d_in[0];
    const float* W1   = (const float*)d_in[1];
    const float* b1   = (const float*)d_in[2];
    const float* W2   = (const float*)d_in[3];
    const float* b2   = (const float*)d_in[4];
    const float* Wif  = (const float*)d_in[5];
    const float* bif  = (const float*)d_in[6];
    const float* Wout = (const float*)d_in[7];
    const float* Wmem = (const float*)d_in[8];
    float* out = (float*)d_out;

    cudaFuncSetAttribute(dnc_kernel, cudaFuncAttributeMaxDynamicSharedMemorySize,
                         (int)sizeof(SMem));
    repack_kernel<<<256, IFP>>>(Wif);

    cudaLaunchConfig_t cfg = {};
    cfg.gridDim = dim3(Bn * 2, 1, 1);
    cfg.blockDim = dim3(NT, 1, 1);
    cfg.dynamicSmemBytes = sizeof(SMem);
    cudaLaunchAttribute attrs[1];
    attrs[0].id = cudaLaunchAttributeClusterDimension;
    attrs[0].val.clusterDim.x = 2;
    attrs[0].val.clusterDim.y = 1;
    attrs[0].val.clusterDim.z = 1;
    cfg.attrs = attrs;
    cfg.numAttrs = 1;
    cudaLaunchKernelEx(&cfg, dnc_kernel, x, W1, b1, W2, b2, bif, Wout, Wmem, out);
}